// round 5
// baseline (speedup 1.0000x reference)
#include <cuda_runtime.h>
#include <math.h>

#define N_TOK 6912      // 256 patches * 27 voxels
#define D     256
#define FF    1024
#define V     27
#define NLAYERS 3

// ---------------- scratch (device globals; no allocation allowed) ----------------
__device__ float g_t [N_TOK * D];
__device__ float g_tn[N_TOK * D];
__device__ float g_q [N_TOK * D];
__device__ float g_k [N_TOK * D];
__device__ float g_v [N_TOK * D];
__device__ float g_ao[N_TOK * D];
__device__ float g_h [N_TOK * FF];
__device__ unsigned g_mask[N_TOK];
__device__ int g_maskmode;   // 0=int32, 1=float32, 2=byte

// ---------------- helpers ----------------
__device__ __forceinline__ float warpSum(float x) {
    #pragma unroll
    for (int o = 16; o; o >>= 1) x += __shfl_xor_sync(0xffffffffu, x, o);
    return x;
}
__device__ __forceinline__ float warpMax(float x) {
    #pragma unroll
    for (int o = 16; o; o >>= 1) x = fmaxf(x, __shfl_xor_sync(0xffffffffu, x, o));
    return x;
}

// ---------------- embedding: x = bit*w_in + b_in + pos_embed ----------------
__global__ void __launch_bounds__(256) embed_kernel(
    const float* __restrict__ npat, const float* __restrict__ w_in,
    const float* __restrict__ b_in, const float* __restrict__ pos,
    float* __restrict__ t)
{
    int n = blockIdx.x;            // token
    int d = threadIdx.x;
    float bit = npat[n];           // [B,1,3,3,3] flat == token index
    int p = n % V;
    t[n * D + d] = bit * w_in[d] + b_in[d] + pos[p * D + d];
}

// ---------------- mask dtype detection ----------------
__global__ void mask_detect(const unsigned* __restrict__ km)
{
    __shared__ int sW, sF;
    if (threadIdx.x == 0) { sW = 0; sF = 0; }
    __syncthreads();
    int w = 0, f = 0;
    for (int i = threadIdx.x; i < N_TOK / 4; i += 256) {
        unsigned x = km[i];
        if (x == 0x3F800000u) f = 1;
        else if (x > 1u) w = 1;
    }
    if (w) atomicOr(&sW, 1);
    if (f) atomicOr(&sF, 1);
    __syncthreads();
    if (threadIdx.x == 0) g_maskmode = sW ? 2 : (sF ? 1 : 0);
}

// ---------------- build 27-bit window mask per token ----------------
__global__ void __launch_bounds__(256) mask_build(const void* __restrict__ km,
                                                  unsigned* __restrict__ mb)
{
    int n = blockIdx.x * blockDim.x + threadIdx.x;
    if (n >= N_TOK) return;
    int mode = g_maskmode;
    int b = n / V, c = n % V;
    int dc = c / 9, hc = (c % 9) / 3, wc = c % 3;
    unsigned bits = 0;
    #pragma unroll
    for (int l = 0; l < V; l++) {
        int nd = dc + l / 9 - 1;
        int nh = hc + (l % 9) / 3 - 1;
        int nw = wc + l % 3 - 1;
        if (nd < 0 || nd > 2 || nh < 0 || nh > 2 || nw < 0 || nw > 2) continue;
        int idx = b * V + nd * 9 + nh * 3 + nw;
        int val;
        if (mode == 2)      val = ((const unsigned char*)km)[idx] != 0;
        else if (mode == 1) val = ((const float*)km)[idx] != 0.0f;
        else                val = ((const int*)km)[idx] != 0;
        if (val) bits |= (1u << l);
    }
    mb[n] = bits;
}

// ---------------- layernorm ----------------
__global__ void __launch_bounds__(256) ln_kernel(
    const float* __restrict__ x, const float* __restrict__ g,
    const float* __restrict__ b, float* __restrict__ y)
{
    int row = blockIdx.x, tidx = threadIdx.x;
    float val = x[row * D + tidx];
    __shared__ float s1[8], s2[8];
    float sum = val, sq = val * val;
    #pragma unroll
    for (int o = 16; o; o >>= 1) {
        sum += __shfl_xor_sync(0xffffffffu, sum, o);
        sq  += __shfl_xor_sync(0xffffffffu, sq,  o);
    }
    if ((tidx & 31) == 0) { s1[tidx >> 5] = sum; s2[tidx >> 5] = sq; }
    __syncthreads();
    sum = 0.f; sq = 0.f;
    #pragma unroll
    for (int i = 0; i < 8; i++) { sum += s1[i]; sq += s2[i]; }
    float mu  = sum * (1.0f / D);
    float var = sq  * (1.0f / D) - mu * mu;
    y[row * D + tidx] = (val - mu) * rsqrtf(var + 1e-5f) * g[tidx] + b[tidx];
}

// ---------------- tiled SGEMM: C[M,Nd] = A[M,K] @ W[K,Nd] + bias (+epilogue) ----
// 128x64x16 tile, 256 threads, 8x4 per thread. Padded smem, LDS.128 reads,
// global->register prefetch (double-buffer in regs) to hide L2 latency.
// EPI: 0 = bias, 1 = bias + residual (C += ...), 2 = bias + exact gelu
template <int EPI>
__global__ void __launch_bounds__(256) gemm_kernel(
    const float* __restrict__ A, const float* __restrict__ W,
    const float* __restrict__ bias, float* __restrict__ C,
    int M, int K, int Nd)
{
    const int BM = 128, BN = 64, BK = 16;
    __shared__ __align__(16) float As[BK][BM + 4];   // 132 floats/row (16B-aligned rows)
    __shared__ __align__(16) float Bs[BK][BN + 4];   // 68 floats/row (16B-aligned rows)
    int m0 = blockIdx.y * BM, n0 = blockIdx.x * BN;
    int tid = threadIdx.x;
    int ty = tid / 16, tx = tid % 16;    // ty: 8-row chunk, tx: 4-col chunk

    // per-thread load coordinates (fixed across k0)
    int arow0 = tid >> 2;                // A rows: arow0 and arow0+64
    int akc4  = tid & 3;                 //   k-quad within tile
    int bkk   = tid / 16;                // B row within tile
    int bnc4  = tid % 16;                //   col-quad

    const float* Aptr0 = &A[(size_t)(m0 + arow0)      * K + akc4 * 4];
    const float* Aptr1 = &A[(size_t)(m0 + arow0 + 64) * K + akc4 * 4];
    const float* Bptr  = &W[(size_t)bkk * Nd + n0 + bnc4 * 4];

    float acc[8][4] = {};
    float4 ra0 = *reinterpret_cast<const float4*>(Aptr0);
    float4 ra1 = *reinterpret_cast<const float4*>(Aptr1);
    float4 rb  = *reinterpret_cast<const float4*>(Bptr);

    for (int k0 = 0; k0 < K; k0 += BK) {
        // store prefetched regs to smem (A transposed)
        As[akc4 * 4 + 0][arow0]      = ra0.x;
        As[akc4 * 4 + 1][arow0]      = ra0.y;
        As[akc4 * 4 + 2][arow0]      = ra0.z;
        As[akc4 * 4 + 3][arow0]      = ra0.w;
        As[akc4 * 4 + 0][arow0 + 64] = ra1.x;
        As[akc4 * 4 + 1][arow0 + 64] = ra1.y;
        As[akc4 * 4 + 2][arow0 + 64] = ra1.z;
        As[akc4 * 4 + 3][arow0 + 64] = ra1.w;
        *reinterpret_cast<float4*>(&Bs[bkk][bnc4 * 4]) = rb;
        __syncthreads();

        // issue next tile's global loads (in flight during compute)
        if (k0 + BK < K) {
            ra0 = *reinterpret_cast<const float4*>(Aptr0 + (k0 + BK));
            ra1 = *reinterpret_cast<const float4*>(Aptr1 + (k0 + BK));
            rb  = *reinterpret_cast<const float4*>(Bptr + (size_t)(k0 + BK) * Nd);
        }

        #pragma unroll
        for (int kk = 0; kk < BK; kk++) {
            float4 a_lo = *reinterpret_cast<const float4*>(&As[kk][ty * 8]);
            float4 a_hi = *reinterpret_cast<const float4*>(&As[kk][ty * 8 + 4]);
            float4 b4   = *reinterpret_cast<const float4*>(&Bs[kk][tx * 4]);
            float a[8] = {a_lo.x, a_lo.y, a_lo.z, a_lo.w, a_hi.x, a_hi.y, a_hi.z, a_hi.w};
            float b[4] = {b4.x, b4.y, b4.z, b4.w};
            #pragma unroll
            for (int i = 0; i < 8; i++)
                #pragma unroll
                for (int j = 0; j < 4; j++)
                    acc[i][j] += a[i] * b[j];
        }
        __syncthreads();
    }

    #pragma unroll
    for (int i = 0; i < 8; i++) {
        int gm = m0 + ty * 8 + i;
        #pragma unroll
        for (int j = 0; j < 4; j++) {
            int gn = n0 + tx * 4 + j;
            float vv = acc[i][j] + bias[gn];
            if (EPI == 1) vv += C[(size_t)gm * Nd + gn];
            if (EPI == 2) vv = 0.5f * vv * (1.0f + erff(vv * 0.7071067811865475f));
            C[(size_t)gm * Nd + gn] = vv;
        }
    }
}

// ---------------- windowed attention: warp per head, block per token --------
__global__ void __launch_bounds__(256) attn_kernel(
    const float* __restrict__ q, const float* __restrict__ k,
    const float* __restrict__ v, const unsigned* __restrict__ mb,
    float* __restrict__ ao)
{
    int n = blockIdx.x;
    int h = threadIdx.x >> 5, lane = threadIdx.x & 31;
    int b = n / V, c = n % V;
    int dc = c / 9, hc = (c % 9) / 3, wc = c % 3;
    unsigned bits = mb[n];
    const float scale = 0.17677669529663687f;   // 1/sqrt(32)

    float qv = q[n * D + h * 32 + lane];
    float s_mine = -1e30f;

    #pragma unroll
    for (int l = 0; l < V; l++) {
        if (!((bits >> l) & 1)) continue;        // uniform across warp
        int nd = dc + l / 9 - 1, nh = hc + (l % 9) / 3 - 1, nw = wc + l % 3 - 1;
        int nn = b * V + nd * 9 + nh * 3 + nw;
        float p = qv * k[nn * D + h * 32 + lane];
        float s = warpSum(p) * scale;
        if (lane == l) s_mine = s;
    }

    float m = warpMax(s_mine);
    float e = (s_mine > -1e29f) ? __expf(s_mine - m) : 0.0f;
    float denom = warpSum(e);
    float a_mine = (denom > 0.0f) ? e / denom : 0.0f;

    float o = 0.0f;
    #pragma unroll
    for (int l = 0; l < V; l++) {
        float al = __shfl_sync(0xffffffffu, a_mine, l);
        if (!((bits >> l) & 1)) continue;        // uniform across warp
        if (al == 0.0f) continue;
        int nd = dc + l / 9 - 1, nh = hc + (l % 9) / 3 - 1, nw = wc + l % 3 - 1;
        int nn = b * V + nd * 9 + nh * 3 + nw;
        o += al * v[nn * D + h * 32 + lane];
    }
    ao[n * D + h * 32 + lane] = o;
}

// ---------------- final projection: out[b] = t[center] . w_out + b_out -----
__global__ void __launch_bounds__(256) out_kernel(
    const float* __restrict__ t, const float* __restrict__ wout,
    const float* __restrict__ bout, float* __restrict__ out)
{
    int b = blockIdx.x, tidx = threadIdx.x;
    float val = t[(b * V + 13) * D + tidx] * wout[tidx];
    __shared__ float s1[8];
    #pragma unroll
    for (int o = 16; o; o >>= 1) val += __shfl_xor_sync(0xffffffffu, val, o);
    if ((tidx & 31) == 0) s1[tidx >> 5] = val;
    __syncthreads();
    if (tidx == 0) {
        float s = 0.f;
        #pragma unroll
        for (int i = 0; i < 8; i++) s += s1[i];
        out[b] = s + bout[0];
    }
}

// ---------------- launch ----------------
extern "C" void kernel_launch(void* const* d_in, const int* in_sizes, int n_in,
                              void* d_out, int out_size)
{
    const float* npat = (const float*)d_in[0];
    const void*  km   = d_in[1];
    const float* w_in = (const float*)d_in[2];
    const float* b_in = (const float*)d_in[3];
    const float* pos  = (const float*)d_in[4];
    const float* ln1g = (const float*)d_in[5];
    const float* ln1b = (const float*)d_in[6];
    const float* ln2g = (const float*)d_in[7];
    const float* ln2b = (const float*)d_in[8];
    const float* Wq = (const float*)d_in[9];  const float* bq = (const float*)d_in[10];
    const float* Wk = (const float*)d_in[11]; const float* bk = (const float*)d_in[12];
    const float* Wv = (const float*)d_in[13]; const float* bv = (const float*)d_in[14];
    const float* Wo = (const float*)d_in[15]; const float* bo = (const float*)d_in[16];
    const float* W1 = (const float*)d_in[17]; const float* b1 = (const float*)d_in[18];
    const float* W2 = (const float*)d_in[19]; const float* b2 = (const float*)d_in[20];
    const float* wout = (const float*)d_in[21];
    const float* bout = (const float*)d_in[22];
    float* out = (float*)d_out;

    float *t, *tn, *q, *k, *v, *ao, *h;
    unsigned* mask;
    cudaGetSymbolAddress((void**)&t,  g_t);
    cudaGetSymbolAddress((void**)&tn, g_tn);
    cudaGetSymbolAddress((void**)&q,  g_q);
    cudaGetSymbolAddress((void**)&k,  g_k);
    cudaGetSymbolAddress((void**)&v,  g_v);
    cudaGetSymbolAddress((void**)&ao, g_ao);
    cudaGetSymbolAddress((void**)&h,  g_h);
    cudaGetSymbolAddress((void**)&mask, g_mask);

    embed_kernel<<<N_TOK, 256>>>(npat, w_in, b_in, pos, t);
    mask_detect<<<1, 256>>>((const unsigned*)km);
    mask_build<<<(N_TOK + 255) / 256, 256>>>(km, mask);

    dim3 gD(D / 64, N_TOK / 128);     // (4,54)  = 216 blocks
    dim3 gF1(FF / 64, N_TOK / 128);   // (16,54) = 864 blocks

    for (int l = 0; l < NLAYERS; l++) {
        const float* wq = Wq + (size_t)l * D * D;   const float* vbq = bq + l * D;
        const float* wk = Wk + (size_t)l * D * D;   const float* vbk = bk + l * D;
        const float* wv = Wv + (size_t)l * D * D;   const float* vbv = bv + l * D;
        const float* wo = Wo + (size_t)l * D * D;   const float* vbo = bo + l * D;
        const float* w1 = W1 + (size_t)l * D * FF;  const float* vb1 = b1 + l * FF;
        const float* w2 = W2 + (size_t)l * FF * D;  const float* vb2 = b2 + l * D;

        ln_kernel<<<N_TOK, 256>>>(t, ln1g + l * D, ln1b + l * D, tn);
        gemm_kernel<0><<<gD, 256>>>(tn, wq, vbq, q, N_TOK, D, D);
        gemm_kernel<0><<<gD, 256>>>(t,  wk, vbk, k, N_TOK, D, D);   // K/V from RAW t
        gemm_kernel<0><<<gD, 256>>>(t,  wv, vbv, v, N_TOK, D, D);
        attn_kernel<<<N_TOK, 256>>>(q, k, v, mask, ao);
        gemm_kernel<1><<<gD, 256>>>(ao, wo, vbo, t, N_TOK, D, D);   // residual add
        ln_kernel<<<N_TOK, 256>>>(t, ln2g + l * D, ln2b + l * D, tn);
        gemm_kernel<2><<<gF1, 256>>>(tn, w1, vb1, h, N_TOK, D, FF); // gelu
        gemm_kernel<1><<<gD, 256>>>(h, w2, vb2, t, N_TOK, FF, D);   // residual add
    }

    out_kernel<<<256, 256>>>(t, wout, bout, out);
}

// round 6
// speedup vs baseline: 1.6936x; 1.6936x over previous
#include <cuda_runtime.h>
#include <math.h>

#define N_TOK 6912      // 256 patches * 27 voxels
#define D     256
#define FF    1024
#define V     27
#define NLAYERS 3

// ---------------- scratch (device globals; no allocation allowed) ----------------
__device__ float g_t [N_TOK * D];
__device__ float g_tn[N_TOK * D];
__device__ float g_q [N_TOK * D];
__device__ float g_k [N_TOK * D];
__device__ float g_v [N_TOK * D];
__device__ float g_ao[N_TOK * D];
__device__ float g_h [N_TOK * FF];
__device__ unsigned g_mask[N_TOK];
__device__ int g_maskmode;   // 0=int32, 1=float32, 2=byte

// ---------------- helpers ----------------
__device__ __forceinline__ float warpSum(float x) {
    #pragma unroll
    for (int o = 16; o; o >>= 1) x += __shfl_xor_sync(0xffffffffu, x, o);
    return x;
}
__device__ __forceinline__ float warpMax(float x) {
    #pragma unroll
    for (int o = 16; o; o >>= 1) x = fmaxf(x, __shfl_xor_sync(0xffffffffu, x, o));
    return x;
}
__device__ __forceinline__ unsigned f2tf32(float f) {
    unsigned r;
    asm("cvt.rna.tf32.f32 %0, %1;" : "=r"(r) : "f"(f));
    return r;
}

#define MMA_TF32(d0,d1,d2,d3,a0,a1,a2,a3,b0,b1) \
  asm volatile("mma.sync.aligned.m16n8k8.row.col.f32.tf32.tf32.f32 " \
    "{%0,%1,%2,%3}, {%4,%5,%6,%7}, {%8,%9}, {%0,%1,%2,%3};" \
    : "+f"(d0),"+f"(d1),"+f"(d2),"+f"(d3) \
    : "r"(a0),"r"(a1),"r"(a2),"r"(a3),"r"(b0),"r"(b1))

// ---------------- embedding: x = bit*w_in + b_in + pos_embed ----------------
__global__ void __launch_bounds__(256) embed_kernel(
    const float* __restrict__ npat, const float* __restrict__ w_in,
    const float* __restrict__ b_in, const float* __restrict__ pos,
    float* __restrict__ t)
{
    int n = blockIdx.x;
    int d = threadIdx.x;
    float bit = npat[n];
    int p = n % V;
    t[n * D + d] = bit * w_in[d] + b_in[d] + pos[p * D + d];
}

// ---------------- mask dtype detection ----------------
__global__ void mask_detect(const unsigned* __restrict__ km)
{
    __shared__ int sW, sF;
    if (threadIdx.x == 0) { sW = 0; sF = 0; }
    __syncthreads();
    int w = 0, f = 0;
    for (int i = threadIdx.x; i < N_TOK / 4; i += 256) {
        unsigned x = km[i];
        if (x == 0x3F800000u) f = 1;
        else if (x > 1u) w = 1;
    }
    if (w) atomicOr(&sW, 1);
    if (f) atomicOr(&sF, 1);
    __syncthreads();
    if (threadIdx.x == 0) g_maskmode = sW ? 2 : (sF ? 1 : 0);
}

// ---------------- build 27-bit window mask per token ----------------
__global__ void __launch_bounds__(256) mask_build(const void* __restrict__ km,
                                                  unsigned* __restrict__ mb)
{
    int n = blockIdx.x * blockDim.x + threadIdx.x;
    if (n >= N_TOK) return;
    int mode = g_maskmode;
    int b = n / V, c = n % V;
    int dc = c / 9, hc = (c % 9) / 3, wc = c % 3;
    unsigned bits = 0;
    #pragma unroll
    for (int l = 0; l < V; l++) {
        int nd = dc + l / 9 - 1;
        int nh = hc + (l % 9) / 3 - 1;
        int nw = wc + l % 3 - 1;
        if (nd < 0 || nd > 2 || nh < 0 || nh > 2 || nw < 0 || nw > 2) continue;
        int idx = b * V + nd * 9 + nh * 3 + nw;
        int val;
        if (mode == 2)      val = ((const unsigned char*)km)[idx] != 0;
        else if (mode == 1) val = ((const float*)km)[idx] != 0.0f;
        else                val = ((const int*)km)[idx] != 0;
        if (val) bits |= (1u << l);
    }
    mb[n] = bits;
}

// ---------------- layernorm ----------------
__global__ void __launch_bounds__(256) ln_kernel(
    const float* __restrict__ x, const float* __restrict__ g,
    const float* __restrict__ b, float* __restrict__ y)
{
    int row = blockIdx.x, tidx = threadIdx.x;
    float val = x[row * D + tidx];
    __shared__ float s1[8], s2[8];
    float sum = val, sq = val * val;
    #pragma unroll
    for (int o = 16; o; o >>= 1) {
        sum += __shfl_xor_sync(0xffffffffu, sum, o);
        sq  += __shfl_xor_sync(0xffffffffu, sq,  o);
    }
    if ((tidx & 31) == 0) { s1[tidx >> 5] = sum; s2[tidx >> 5] = sq; }
    __syncthreads();
    sum = 0.f; sq = 0.f;
    #pragma unroll
    for (int i = 0; i < 8; i++) { sum += s1[i]; sq += s2[i]; }
    float mu  = sum * (1.0f / D);
    float var = sq  * (1.0f / D) - mu * mu;
    y[row * D + tidx] = (val - mu) * rsqrtf(var + 1e-5f) * g[tidx] + b[tidx];
}

// ---------------- TF32 tensor-core GEMM -------------------------------------
// C[M,Nd] = A[M,K] @ W[K,Nd] + bias (+epilogue), via mma.m16n8k8 tf32.
// 128x64x32 block tile, 8 warps (4m x 2n), warp tile 32x32 (2x4 frags).
// EPI: 0 = bias, 1 = bias + residual, 2 = bias + exact gelu
template <int EPI>
__global__ void __launch_bounds__(256) gemm_tc(
    const float* __restrict__ A, const float* __restrict__ W,
    const float* __restrict__ bias, float* __restrict__ C,
    int M, int K, int Nd)
{
    const int BM = 128, BN = 64, BK = 32;
    __shared__ unsigned As[BM][BK + 4];   // stride 36: frag reads conflict-free
    __shared__ unsigned Bs[BK][BN + 8];   // stride 72: frag reads conflict-free
    int m0 = blockIdx.y * BM, n0 = blockIdx.x * BN;
    int tid = threadIdx.x;
    int warp = tid >> 5, lane = tid & 31;
    int wm = (warp >> 1) * 32, wn = (warp & 1) * 32;
    int g = lane >> 2, tg = lane & 3;

    float acc[2][4][4] = {};

    // prefetch regs (global -> reg -> smem pipeline)
    float4 ra[4], rb[2];
    #pragma unroll
    for (int t = 0; t < 4; t++) {
        int i = tid + t * 256, row = i >> 3, c4 = i & 7;
        ra[t] = *reinterpret_cast<const float4*>(&A[(size_t)(m0 + row) * K + c4 * 4]);
    }
    #pragma unroll
    for (int t = 0; t < 2; t++) {
        int i = tid + t * 256, row = i >> 4, c4 = i & 15;
        rb[t] = *reinterpret_cast<const float4*>(&W[(size_t)row * Nd + n0 + c4 * 4]);
    }

    for (int k0 = 0; k0 < K; k0 += BK) {
        // store prefetched regs to smem, rounding to tf32 (rna) once
        #pragma unroll
        for (int t = 0; t < 4; t++) {
            int i = tid + t * 256, row = i >> 3, c4 = i & 7;
            As[row][c4 * 4 + 0] = f2tf32(ra[t].x);
            As[row][c4 * 4 + 1] = f2tf32(ra[t].y);
            As[row][c4 * 4 + 2] = f2tf32(ra[t].z);
            As[row][c4 * 4 + 3] = f2tf32(ra[t].w);
        }
        #pragma unroll
        for (int t = 0; t < 2; t++) {
            int i = tid + t * 256, row = i >> 4, c4 = i & 15;
            Bs[row][c4 * 4 + 0] = f2tf32(rb[t].x);
            Bs[row][c4 * 4 + 1] = f2tf32(rb[t].y);
            Bs[row][c4 * 4 + 2] = f2tf32(rb[t].z);
            Bs[row][c4 * 4 + 3] = f2tf32(rb[t].w);
        }
        __syncthreads();

        // next tile's global loads in flight during the mma work
        if (k0 + BK < K) {
            #pragma unroll
            for (int t = 0; t < 4; t++) {
                int i = tid + t * 256, row = i >> 3, c4 = i & 7;
                ra[t] = *reinterpret_cast<const float4*>(
                    &A[(size_t)(m0 + row) * K + k0 + BK + c4 * 4]);
            }
            #pragma unroll
            for (int t = 0; t < 2; t++) {
                int i = tid + t * 256, row = i >> 4, c4 = i & 15;
                rb[t] = *reinterpret_cast<const float4*>(
                    &W[(size_t)(k0 + BK + row) * Nd + n0 + c4 * 4]);
            }
        }

        #pragma unroll
        for (int ks = 0; ks < 4; ks++) {
            int kb = ks * 8;
            unsigned af[2][4], bf[4][2];
            #pragma unroll
            for (int i = 0; i < 2; i++) {
                int r = wm + i * 16;
                af[i][0] = As[r + g][kb + tg];
                af[i][1] = As[r + g + 8][kb + tg];
                af[i][2] = As[r + g][kb + tg + 4];
                af[i][3] = As[r + g + 8][kb + tg + 4];
            }
            #pragma unroll
            for (int j = 0; j < 4; j++) {
                int cn = wn + j * 8 + g;
                bf[j][0] = Bs[kb + tg][cn];
                bf[j][1] = Bs[kb + tg + 4][cn];
            }
            #pragma unroll
            for (int i = 0; i < 2; i++)
                #pragma unroll
                for (int j = 0; j < 4; j++)
                    MMA_TF32(acc[i][j][0], acc[i][j][1], acc[i][j][2], acc[i][j][3],
                             af[i][0], af[i][1], af[i][2], af[i][3],
                             bf[j][0], bf[j][1]);
        }
        __syncthreads();
    }

    // epilogue
    #pragma unroll
    for (int i = 0; i < 2; i++) {
        int r0 = m0 + wm + i * 16 + g;
        #pragma unroll
        for (int j = 0; j < 4; j++) {
            int c0 = n0 + wn + j * 8 + tg * 2;
            #pragma unroll
            for (int e = 0; e < 4; e++) {
                int gm = r0 + (e >> 1) * 8;
                int gn = c0 + (e & 1);
                float vv = acc[i][j][e] + bias[gn];
                if (EPI == 1) vv += C[(size_t)gm * Nd + gn];
                if (EPI == 2) vv = 0.5f * vv * (1.0f + erff(vv * 0.7071067811865475f));
                C[(size_t)gm * Nd + gn] = vv;
            }
        }
    }
}

// ---------------- windowed attention: warp per head, block per token --------
__global__ void __launch_bounds__(256) attn_kernel(
    const float* __restrict__ q, const float* __restrict__ k,
    const float* __restrict__ v, const unsigned* __restrict__ mb,
    float* __restrict__ ao)
{
    int n = blockIdx.x;
    int h = threadIdx.x >> 5, lane = threadIdx.x & 31;
    int b = n / V, c = n % V;
    int dc = c / 9, hc = (c % 9) / 3, wc = c % 3;
    unsigned bits = mb[n];
    const float scale = 0.17677669529663687f;   // 1/sqrt(32)

    float qv = q[n * D + h * 32 + lane];
    float s_mine = -1e30f;

    #pragma unroll
    for (int l = 0; l < V; l++) {
        if (!((bits >> l) & 1)) continue;
        int nd = dc + l / 9 - 1, nh = hc + (l % 9) / 3 - 1, nw = wc + l % 3 - 1;
        int nn = b * V + nd * 9 + nh * 3 + nw;
        float p = qv * k[nn * D + h * 32 + lane];
        float s = warpSum(p) * scale;
        if (lane == l) s_mine = s;
    }

    float m = warpMax(s_mine);
    float e = (s_mine > -1e29f) ? __expf(s_mine - m) : 0.0f;
    float denom = warpSum(e);
    float a_mine = (denom > 0.0f) ? e / denom : 0.0f;

    float o = 0.0f;
    #pragma unroll
    for (int l = 0; l < V; l++) {
        float al = __shfl_sync(0xffffffffu, a_mine, l);
        if (!((bits >> l) & 1)) continue;
        if (al == 0.0f) continue;
        int nd = dc + l / 9 - 1, nh = hc + (l % 9) / 3 - 1, nw = wc + l % 3 - 1;
        int nn = b * V + nd * 9 + nh * 3 + nw;
        o += al * v[nn * D + h * 32 + lane];
    }
    ao[n * D + h * 32 + lane] = o;
}

// ---------------- final projection: out[b] = t[center] . w_out + b_out -----
__global__ void __launch_bounds__(256) out_kernel(
    const float* __restrict__ t, const float* __restrict__ wout,
    const float* __restrict__ bout, float* __restrict__ out)
{
    int b = blockIdx.x, tidx = threadIdx.x;
    float val = t[(b * V + 13) * D + tidx] * wout[tidx];
    __shared__ float s1[8];
    #pragma unroll
    for (int o = 16; o; o >>= 1) val += __shfl_xor_sync(0xffffffffu, val, o);
    if ((tidx & 31) == 0) s1[tidx >> 5] = val;
    __syncthreads();
    if (tidx == 0) {
        float s = 0.f;
        #pragma unroll
        for (int i = 0; i < 8; i++) s += s1[i];
        out[b] = s + bout[0];
    }
}

// ---------------- launch ----------------
extern "C" void kernel_launch(void* const* d_in, const int* in_sizes, int n_in,
                              void* d_out, int out_size)
{
    const float* npat = (const float*)d_in[0];
    const void*  km   = d_in[1];
    const float* w_in = (const float*)d_in[2];
    const float* b_in = (const float*)d_in[3];
    const float* pos  = (const float*)d_in[4];
    const float* ln1g = (const float*)d_in[5];
    const float* ln1b = (const float*)d_in[6];
    const float* ln2g = (const float*)d_in[7];
    const float* ln2b = (const float*)d_in[8];
    const float* Wq = (const float*)d_in[9];  const float* bq = (const float*)d_in[10];
    const float* Wk = (const float*)d_in[11]; const float* bk = (const float*)d_in[12];
    const float* Wv = (const float*)d_in[13]; const float* bv = (const float*)d_in[14];
    const float* Wo = (const float*)d_in[15]; const float* bo = (const float*)d_in[16];
    const float* W1 = (const float*)d_in[17]; const float* b1 = (const float*)d_in[18];
    const float* W2 = (const float*)d_in[19]; const float* b2 = (const float*)d_in[20];
    const float* wout = (const float*)d_in[21];
    const float* bout = (const float*)d_in[22];
    float* out = (float*)d_out;

    float *t, *tn, *q, *k, *v, *ao, *h;
    unsigned* mask;
    cudaGetSymbolAddress((void**)&t,  g_t);
    cudaGetSymbolAddress((void**)&tn, g_tn);
    cudaGetSymbolAddress((void**)&q,  g_q);
    cudaGetSymbolAddress((void**)&k,  g_k);
    cudaGetSymbolAddress((void**)&v,  g_v);
    cudaGetSymbolAddress((void**)&ao, g_ao);
    cudaGetSymbolAddress((void**)&h,  g_h);
    cudaGetSymbolAddress((void**)&mask, g_mask);

    embed_kernel<<<N_TOK, 256>>>(npat, w_in, b_in, pos, t);
    mask_detect<<<1, 256>>>((const unsigned*)km);
    mask_build<<<(N_TOK + 255) / 256, 256>>>(km, mask);

    dim3 gD(D / 64, N_TOK / 128);     // (4,54)
    dim3 gF1(FF / 64, N_TOK / 128);   // (16,54)

    for (int l = 0; l < NLAYERS; l++) {
        const float* wq = Wq + (size_t)l * D * D;   const float* vbq = bq + l * D;
        const float* wk = Wk + (size_t)l * D * D;   const float* vbk = bk + l * D;
        const float* wv = Wv + (size_t)l * D * D;   const float* vbv = bv + l * D;
        const float* wo = Wo + (size_t)l * D * D;   const float* vbo = bo + l * D;
        const float* w1 = W1 + (size_t)l * D * FF;  const float* vb1 = b1 + l * FF;
        const float* w2 = W2 + (size_t)l * FF * D;  const float* vb2 = b2 + l * D;

        ln_kernel<<<N_TOK, 256>>>(t, ln1g + l * D, ln1b + l * D, tn);
        gemm_tc<0><<<gD, 256>>>(tn, wq, vbq, q, N_TOK, D, D);
        gemm_tc<0><<<gD, 256>>>(t,  wk, vbk, k, N_TOK, D, D);   // K/V from RAW t
        gemm_tc<0><<<gD, 256>>>(t,  wv, vbv, v, N_TOK, D, D);
        attn_kernel<<<N_TOK, 256>>>(q, k, v, mask, ao);
        gemm_tc<1><<<gD, 256>>>(ao, wo, vbo, t, N_TOK, D, D);   // residual add
        ln_kernel<<<N_TOK, 256>>>(t, ln2g + l * D, ln2b + l * D, tn);
        gemm_tc<2><<<gF1, 256>>>(tn, w1, vb1, h, N_TOK, D, FF); // gelu
        gemm_tc<1><<<gD, 256>>>(h, w2, vb2, t, N_TOK, FF, D);   // residual add
    }

    out_kernel<<<256, 256>>>(t, wout, bout, out);
}

// round 15
// speedup vs baseline: 1.7905x; 1.0573x over previous
#include <cuda_runtime.h>
#include <cuda_fp16.h>
#include <math.h>
#include <stdint.h>

#define N_TOK 6912      // 256 patches * 27 voxels
#define D     256
#define FF    1024
#define V     27
#define NLAYERS 3

// ---------------- scratch (device globals; no allocation allowed) ----------------
__device__ float g_t [N_TOK * D];
__device__ float g_tn[N_TOK * D];
__device__ float g_q [N_TOK * D];
__device__ float g_k [N_TOK * D];
__device__ float g_v [N_TOK * D];
__device__ float g_ao[N_TOK * D];
__device__ float g_h [N_TOK * FF];
__device__ unsigned g_mask[N_TOK];
__device__ int g_maskmode;   // 0=int32, 1=float32, 2=byte

// ---------------- helpers ----------------
__device__ __forceinline__ float warpSum(float x) {
    #pragma unroll
    for (int o = 16; o; o >>= 1) x += __shfl_xor_sync(0xffffffffu, x, o);
    return x;
}
__device__ __forceinline__ float warpMax(float x) {
    #pragma unroll
    for (int o = 16; o; o >>= 1) x = fmaxf(x, __shfl_xor_sync(0xffffffffu, x, o));
    return x;
}
__device__ __forceinline__ unsigned packh2(float x, float y) {
    __half2 h = __floats2half2_rn(x, y);
    return *reinterpret_cast<unsigned*>(&h);
}

#define MMA_F16(d0,d1,d2,d3,a0,a1,a2,a3,b0,b1) \
  asm volatile("mma.sync.aligned.m16n8k16.row.col.f32.f16.f16.f32 " \
    "{%0,%1,%2,%3}, {%4,%5,%6,%7}, {%8,%9}, {%0,%1,%2,%3};" \
    : "+f"(d0),"+f"(d1),"+f"(d2),"+f"(d3) \
    : "r"(a0),"r"(a1),"r"(a2),"r"(a3),"r"(b0),"r"(b1))

// ---------------- embedding: x = bit*w_in + b_in + pos_embed ----------------
__global__ void __launch_bounds__(256) embed_kernel(
    const float* __restrict__ npat, const float* __restrict__ w_in,
    const float* __restrict__ b_in, const float* __restrict__ pos,
    float* __restrict__ t)
{
    int n = blockIdx.x;
    int d = threadIdx.x;
    float bit = npat[n];
    int p = n % V;
    t[n * D + d] = bit * w_in[d] + b_in[d] + pos[p * D + d];
}

// ---------------- mask dtype detection ----------------
__global__ void mask_detect(const unsigned* __restrict__ km)
{
    __shared__ int sW, sF;
    if (threadIdx.x == 0) { sW = 0; sF = 0; }
    __syncthreads();
    int w = 0, f = 0;
    for (int i = threadIdx.x; i < N_TOK / 4; i += 256) {
        unsigned x = km[i];
        if (x == 0x3F800000u) f = 1;
        else if (x > 1u) w = 1;
    }
    if (w) atomicOr(&sW, 1);
    if (f) atomicOr(&sF, 1);
    __syncthreads();
    if (threadIdx.x == 0) g_maskmode = sW ? 2 : (sF ? 1 : 0);
}

// ---------------- build 27-bit window mask per token ----------------
__global__ void __launch_bounds__(256) mask_build(const void* __restrict__ km,
                                                  unsigned* __restrict__ mb)
{
    int n = blockIdx.x * blockDim.x + threadIdx.x;
    if (n >= N_TOK) return;
    int mode = g_maskmode;
    int b = n / V, c = n % V;
    int dc = c / 9, hc = (c % 9) / 3, wc = c % 3;
    unsigned bits = 0;
    #pragma unroll
    for (int l = 0; l < V; l++) {
        int nd = dc + l / 9 - 1;
        int nh = hc + (l % 9) / 3 - 1;
        int nw = wc + l % 3 - 1;
        if (nd < 0 || nd > 2 || nh < 0 || nh > 2 || nw < 0 || nw > 2) continue;
        int idx = b * V + nd * 9 + nh * 3 + nw;
        int val;
        if (mode == 2)      val = ((const unsigned char*)km)[idx] != 0;
        else if (mode == 1) val = ((const float*)km)[idx] != 0.0f;
        else                val = ((const int*)km)[idx] != 0;
        if (val) bits |= (1u << l);
    }
    mb[n] = bits;
}

// ---------------- layernorm: one warp per row, 8 elems/lane ------------------
__global__ void __launch_bounds__(256) ln_kernel(
    const float* __restrict__ x, const float* __restrict__ g,
    const float* __restrict__ b, float* __restrict__ y)
{
    int warp = threadIdx.x >> 5, lane = threadIdx.x & 31;
    int row = blockIdx.x * 8 + warp;
    const float* xr = &x[(size_t)row * D + lane * 8];
    float4 v0 = *reinterpret_cast<const float4*>(xr);
    float4 v1 = *reinterpret_cast<const float4*>(xr + 4);

    float sum = v0.x + v0.y + v0.z + v0.w + v1.x + v1.y + v1.z + v1.w;
    float sq  = v0.x*v0.x + v0.y*v0.y + v0.z*v0.z + v0.w*v0.w
              + v1.x*v1.x + v1.y*v1.y + v1.z*v1.z + v1.w*v1.w;
    #pragma unroll
    for (int o = 16; o; o >>= 1) {
        sum += __shfl_xor_sync(0xffffffffu, sum, o);
        sq  += __shfl_xor_sync(0xffffffffu, sq,  o);
    }
    float mu  = sum * (1.0f / D);
    float var = sq * (1.0f / D) - mu * mu;
    float rs  = rsqrtf(var + 1e-5f);

    float4 g0 = *reinterpret_cast<const float4*>(&g[lane * 8]);
    float4 g1 = *reinterpret_cast<const float4*>(&g[lane * 8 + 4]);
    float4 b0 = *reinterpret_cast<const float4*>(&b[lane * 8]);
    float4 b1 = *reinterpret_cast<const float4*>(&b[lane * 8 + 4]);

    float4 o0, o1;
    o0.x = (v0.x - mu) * rs * g0.x + b0.x;
    o0.y = (v0.y - mu) * rs * g0.y + b0.y;
    o0.z = (v0.z - mu) * rs * g0.z + b0.z;
    o0.w = (v0.w - mu) * rs * g0.w + b0.w;
    o1.x = (v1.x - mu) * rs * g1.x + b1.x;
    o1.y = (v1.y - mu) * rs * g1.y + b1.y;
    o1.z = (v1.z - mu) * rs * g1.z + b1.z;
    o1.w = (v1.w - mu) * rs * g1.w + b1.w;
    float* yr = &y[(size_t)row * D + lane * 8];
    *reinterpret_cast<float4*>(yr)     = o0;
    *reinterpret_cast<float4*>(yr + 4) = o1;
}

// ---------------- FP16 tensor-core GEMM body --------------------------------
// C[M,Nd] = A[M,K] @ W[K,Nd] + bias (+epilogue), via mma.m16n8k16 f16 (fp32 acc).
// 128x64x32 block tile, 8 warps (4m x 2n), warp tile 32x32 (2x4 frags).
// Smem rows stride 40 halves (80B): fragment reads conflict-free.
// EPI: 0 = bias, 1 = bias + residual, 2 = bias + exact gelu
template <int EPI>
__device__ __forceinline__ void gemm_body(
    __half (*As)[40], __half (*Bs)[40],
    const float* __restrict__ A, const float* __restrict__ W,
    const float* __restrict__ bias, float* __restrict__ C,
    int M, int K, int Nd)
{
    const int BK = 32;
    int m0 = blockIdx.y * 128, n0 = blockIdx.x * 64;
    int tid = threadIdx.x;
    int warp = tid >> 5, lane = tid & 31;
    int wm = (warp >> 1) * 32, wn = (warp & 1) * 32;
    int g = lane >> 2, tg = lane & 3;

    float acc[2][4][4] = {};

    // prefetch regs (global -> reg -> smem pipeline)
    float4 ra[4], rb[2];
    #pragma unroll
    for (int t = 0; t < 4; t++) {
        int i = tid + t * 256, row = i >> 3, c4 = i & 7;
        ra[t] = *reinterpret_cast<const float4*>(&A[(size_t)(m0 + row) * K + c4 * 4]);
    }
    #pragma unroll
    for (int t = 0; t < 2; t++) {
        int i = tid + t * 256, row = i >> 4, c4 = i & 15;
        rb[t] = *reinterpret_cast<const float4*>(&W[(size_t)row * Nd + n0 + c4 * 4]);
    }

    for (int k0 = 0; k0 < K; k0 += BK) {
        // A: store prefetched regs to smem as half2 pairs ([m][k])
        #pragma unroll
        for (int t = 0; t < 4; t++) {
            int i = tid + t * 256, row = i >> 3, c4 = i & 7;
            uint2 h;
            h.x = packh2(ra[t].x, ra[t].y);
            h.y = packh2(ra[t].z, ra[t].w);
            *reinterpret_cast<uint2*>(&As[row][c4 * 4]) = h;
        }
        // B: transpose W[k][n] -> Bs[n][k], half scatter
        #pragma unroll
        for (int t = 0; t < 2; t++) {
            int i = tid + t * 256, krow = i >> 4, c4 = i & 15;
            Bs[c4 * 4 + 0][krow] = __float2half_rn(rb[t].x);
            Bs[c4 * 4 + 1][krow] = __float2half_rn(rb[t].y);
            Bs[c4 * 4 + 2][krow] = __float2half_rn(rb[t].z);
            Bs[c4 * 4 + 3][krow] = __float2half_rn(rb[t].w);
        }
        __syncthreads();

        // next tile's global loads in flight during the mma work
        if (k0 + BK < K) {
            #pragma unroll
            for (int t = 0; t < 4; t++) {
                int i = tid + t * 256, row = i >> 3, c4 = i & 7;
                ra[t] = *reinterpret_cast<const float4*>(
                    &A[(size_t)(m0 + row) * K + k0 + BK + c4 * 4]);
            }
            #pragma unroll
            for (int t = 0; t < 2; t++) {
                int i = tid + t * 256, row = i >> 4, c4 = i & 15;
                rb[t] = *reinterpret_cast<const float4*>(
                    &W[(size_t)(k0 + BK + row) * Nd + n0 + c4 * 4]);
            }
        }

        #pragma unroll
        for (int ks = 0; ks < 2; ks++) {
            int kb = ks * 16;
            unsigned af[2][4], bf[4][2];
            #pragma unroll
            for (int i = 0; i < 2; i++) {
                int r = wm + i * 16;
                af[i][0] = *reinterpret_cast<const unsigned*>(&As[r + g][kb + tg * 2]);
                af[i][1] = *reinterpret_cast<const unsigned*>(&As[r + g + 8][kb + tg * 2]);
                af[i][2] = *reinterpret_cast<const unsigned*>(&As[r + g][kb + tg * 2 + 8]);
                af[i][3] = *reinterpret_cast<const unsigned*>(&As[r + g + 8][kb + tg * 2 + 8]);
            }
            #pragma unroll
            for (int j = 0; j < 4; j++) {
                int cn = wn + j * 8 + g;
                bf[j][0] = *reinterpret_cast<const unsigned*>(&Bs[cn][kb + tg * 2]);
                bf[j][1] = *reinterpret_cast<const unsigned*>(&Bs[cn][kb + tg * 2 + 8]);
            }
            #pragma unroll
            for (int i = 0; i < 2; i++)
                #pragma unroll
                for (int j = 0; j < 4; j++)
                    MMA_F16(acc[i][j][0], acc[i][j][1], acc[i][j][2], acc[i][j][3],
                            af[i][0], af[i][1], af[i][2], af[i][3],
                            bf[j][0], bf[j][1]);
        }
        __syncthreads();
    }

    // epilogue
    #pragma unroll
    for (int i = 0; i < 2; i++) {
        int r0 = m0 + wm + i * 16 + g;
        #pragma unroll
        for (int j = 0; j < 4; j++) {
            int c0 = n0 + wn + j * 8 + tg * 2;
            #pragma unroll
            for (int e = 0; e < 4; e++) {
                int gm = r0 + (e >> 1) * 8;
                int gn = c0 + (e & 1);
                float vv = acc[i][j][e] + bias[gn];
                if (EPI == 1) vv += C[(size_t)gm * Nd + gn];
                if (EPI == 2) vv = 0.5f * vv * (1.0f + erff(vv * 0.7071067811865475f));
                C[(size_t)gm * Nd + gn] = vv;
            }
        }
    }
}

// single-GEMM wrapper
template <int EPI>
__global__ void __launch_bounds__(256) gemm_tc(
    const float* __restrict__ A, const float* __restrict__ W,
    const float* __restrict__ bias, float* __restrict__ C,
    int M, int K, int Nd)
{
    __shared__ __align__(16) __half As[128][40];
    __shared__ __align__(16) __half Bs[64][40];
    gemm_body<EPI>(As, Bs, A, W, bias, C, M, K, Nd);
}

// fused Q/K/V wrapper: blockIdx.z selects which GEMM this CTA computes.
// Q reads tn (LN1 output); K/V read raw t. All ready after ln_kernel.
__global__ void __launch_bounds__(256) gemm_qkv(
    const float* __restrict__ tn, const float* __restrict__ t,
    const float* __restrict__ Wq, const float* __restrict__ bq,
    const float* __restrict__ Wk, const float* __restrict__ bk,
    const float* __restrict__ Wv, const float* __restrict__ bv,
    float* __restrict__ q, float* __restrict__ k, float* __restrict__ v,
    int M, int K, int Nd)
{
    __shared__ __align__(16) __half As[128][40];
    __shared__ __align__(16) __half Bs[64][40];
    if (blockIdx.z == 0)      gemm_body<0>(As, Bs, tn, Wq, bq, q, M, K, Nd);
    else if (blockIdx.z == 1) gemm_body<0>(As, Bs, t,  Wk, bk, k, M, K, Nd);
    else                      gemm_body<0>(As, Bs, t,  Wv, bv, v, M, K, Nd);
}

// ---------------- windowed attention: warp per head, block per token --------
__global__ void __launch_bounds__(256) attn_kernel(
    const float* __restrict__ q, const float* __restrict__ k,
    const float* __restrict__ v, const unsigned* __restrict__ mb,
    float* __restrict__ ao)
{
    int n = blockIdx.x;
    int h = threadIdx.x >> 5, lane = threadIdx.x & 31;
    int b = n / V, c = n % V;
    int dc = c / 9, hc = (c % 9) / 3, wc = c % 3;
    unsigned bits = mb[n];
    const float scale = 0.17677669529663687f;   // 1/sqrt(32)

    float qv = q[n * D + h * 32 + lane];
    float s_mine = -1e30f;

    #pragma unroll
    for (int l = 0; l < V; l++) {
        if (!((bits >> l) & 1)) continue;
        int nd = dc + l / 9 - 1, nh = hc + (l % 9) / 3 - 1, nw = wc + l % 3 - 1;
        int nn = b * V + nd * 9 + nh * 3 + nw;
        float p = qv * k[nn * D + h * 32 + lane];
        float s = warpSum(p) * scale;
        if (lane == l) s_mine = s;
    }

    float m = warpMax(s_mine);
    float e = (s_mine > -1e29f) ? __expf(s_mine - m) : 0.0f;
    float denom = warpSum(e);
    float a_mine = (denom > 0.0f) ? e / denom : 0.0f;

    float o = 0.0f;
    #pragma unroll
    for (int l = 0; l < V; l++) {
        float al = __shfl_sync(0xffffffffu, a_mine, l);
        if (!((bits >> l) & 1)) continue;
        if (al == 0.0f) continue;
        int nd = dc + l / 9 - 1, nh = hc + (l % 9) / 3 - 1, nw = wc + l % 3 - 1;
        int nn = b * V + nd * 9 + nh * 3 + nw;
        o += al * v[nn * D + h * 32 + lane];
    }
    ao[n * D + h * 32 + lane] = o;
}

// ---------------- final projection: out[b] = t[center] . w_out + b_out -----
__global__ void __launch_bounds__(256) out_kernel(
    const float* __restrict__ t, const float* __restrict__ wout,
    const float* __restrict__ bout, float* __restrict__ out)
{
    int b = blockIdx.x, tidx = threadIdx.x;
    float val = t[(b * V + 13) * D + tidx] * wout[tidx];
    __shared__ float s1[8];
    #pragma unroll
    for (int o = 16; o; o >>= 1) val += __shfl_xor_sync(0xffffffffu, val, o);
    if ((tidx & 31) == 0) s1[tidx >> 5] = val;
    __syncthreads();
    if (tidx == 0) {
        float s = 0.f;
        #pragma unroll
        for (int i = 0; i < 8; i++) s += s1[i];
        out[b] = s + bout[0];
    }
}

// ---------------- launch ----------------
extern "C" void kernel_launch(void* const* d_in, const int* in_sizes, int n_in,
                              void* d_out, int out_size)
{
    const float* npat = (const float*)d_in[0];
    const void*  km   = d_in[1];
    const float* w_in = (const float*)d_in[2];
    const float* b_in = (const float*)d_in[3];
    const float* pos  = (const float*)d_in[4];
    const float* ln1g = (const float*)d_in[5];
    const float* ln1b = (const float*)d_in[6];
    const float* ln2g = (const float*)d_in[7];
    const float* ln2b = (const float*)d_in[8];
    const float* Wq = (const float*)d_in[9];  const float* bq = (const float*)d_in[10];
    const float* Wk = (const float*)d_in[11]; const float* bk = (const float*)d_in[12];
    const float* Wv = (const float*)d_in[13]; const float* bv = (const float*)d_in[14];
    const float* Wo = (const float*)d_in[15]; const float* bo = (const float*)d_in[16];
    const float* W1 = (const float*)d_in[17]; const float* b1 = (const float*)d_in[18];
    const float* W2 = (const float*)d_in[19]; const float* b2 = (const float*)d_in[20];
    const float* wout = (const float*)d_in[21];
    const float* bout = (const float*)d_in[22];
    float* out = (float*)d_out;

    float *t, *tn, *q, *k, *v, *ao, *h;
    unsigned* mask;
    cudaGetSymbolAddress((void**)&t,  g_t);
    cudaGetSymbolAddress((void**)&tn, g_tn);
    cudaGetSymbolAddress((void**)&q,  g_q);
    cudaGetSymbolAddress((void**)&k,  g_k);
    cudaGetSymbolAddress((void**)&v,  g_v);
    cudaGetSymbolAddress((void**)&ao, g_ao);
    cudaGetSymbolAddress((void**)&h,  g_h);
    cudaGetSymbolAddress((void**)&mask, g_mask);

    embed_kernel<<<N_TOK, 256>>>(npat, w_in, b_in, pos, t);
    mask_detect<<<1, 256>>>((const unsigned*)km);
    mask_build<<<(N_TOK + 255) / 256, 256>>>(km, mask);

    dim3 gD(D / 64, N_TOK / 128);        // (4,54)
    dim3 gQKV(D / 64, N_TOK / 128, 3);   // (4,54,3)
    dim3 gF1(FF / 64, N_TOK / 128);      // (16,54)

    for (int l = 0; l < NLAYERS; l++) {
        const float* wq = Wq + (size_t)l * D * D;   const float* vbq = bq + l * D;
        const float* wk = Wk + (size_t)l * D * D;   const float* vbk = bk + l * D;
        const float* wv = Wv + (size_t)l * D * D;   const float* vbv = bv + l * D;
        const float* wo = Wo + (size_t)l * D * D;   const float* vbo = bo + l * D;
        const float* w1 = W1 + (size_t)l * D * FF;  const float* vb1 = b1 + l * FF;
        const float* w2 = W2 + (size_t)l * FF * D;  const float* vb2 = b2 + l * D;

        ln_kernel<<<N_TOK / 8, 256>>>(t, ln1g + l * D, ln1b + l * D, tn);
        gemm_qkv<<<gQKV, 256>>>(tn, t, wq, vbq, wk, vbk, wv, vbv,
                                q, k, v, N_TOK, D, D);
        attn_kernel<<<N_TOK, 256>>>(q, k, v, mask, ao);
        gemm_tc<1><<<gD, 256>>>(ao, wo, vbo, t, N_TOK, D, D);   // residual add
        ln_kernel<<<N_TOK / 8, 256>>>(t, ln2g + l * D, ln2b + l * D, tn);
        gemm_tc<2><<<gF1, 256>>>(tn, w1, vb1, h, N_TOK, D, FF); // gelu
        gemm_tc<1><<<gD, 256>>>(h, w2, vb2, t, N_TOK, FF, D);   // residual add
    }

    out_kernel<<<256, 256>>>(t, wout, bout, out);
}

// round 17
// speedup vs baseline: 1.8975x; 1.0598x over previous
#include <cuda_runtime.h>
#include <cuda_fp16.h>
#include <math.h>
#include <stdint.h>

#define N_TOK 6912      // 256 patches * 27 voxels
#define D     256
#define FF    1024
#define V     27
#define NLAYERS 3

// ---------------- scratch (device globals; no allocation allowed) ----------------
__device__ float g_t [N_TOK * D];
__device__ float g_tn[N_TOK * D];
__device__ float g_q [N_TOK * D];
__device__ float g_k [N_TOK * D];
__device__ float g_v [N_TOK * D];
__device__ float g_ao[N_TOK * D];
__device__ float g_h [N_TOK * FF];
__device__ unsigned g_mask[N_TOK];
__device__ int g_maskmode;   // 0=int32, 1=float32, 2=byte

// ---------------- helpers ----------------
__device__ __forceinline__ float warpSum(float x) {
    #pragma unroll
    for (int o = 16; o; o >>= 1) x += __shfl_xor_sync(0xffffffffu, x, o);
    return x;
}
__device__ __forceinline__ float warpMax(float x) {
    #pragma unroll
    for (int o = 16; o; o >>= 1) x = fmaxf(x, __shfl_xor_sync(0xffffffffu, x, o));
    return x;
}
__device__ __forceinline__ unsigned packh2(float x, float y) {
    __half2 h = __floats2half2_rn(x, y);
    return *reinterpret_cast<unsigned*>(&h);
}

#define MMA_F16(d0,d1,d2,d3,a0,a1,a2,a3,b0,b1) \
  asm volatile("mma.sync.aligned.m16n8k16.row.col.f32.f16.f16.f32 " \
    "{%0,%1,%2,%3}, {%4,%5,%6,%7}, {%8,%9}, {%0,%1,%2,%3};" \
    : "+f"(d0),"+f"(d1),"+f"(d2),"+f"(d3) \
    : "r"(a0),"r"(a1),"r"(a2),"r"(a3),"r"(b0),"r"(b1))

#define LDSM_X4(r0,r1,r2,r3,addr) \
  asm volatile("ldmatrix.sync.aligned.m8n8.x4.shared.b16 {%0,%1,%2,%3}, [%4];" \
    : "=r"(r0),"=r"(r1),"=r"(r2),"=r"(r3) : "r"(addr))

// ---------------- embedding: x = bit*w_in + b_in + pos_embed ----------------
__global__ void __launch_bounds__(256) embed_kernel(
    const float* __restrict__ npat, const float* __restrict__ w_in,
    const float* __restrict__ b_in, const float* __restrict__ pos,
    float* __restrict__ t)
{
    int n = blockIdx.x;
    int d = threadIdx.x;
    float bit = npat[n];
    int p = n % V;
    t[n * D + d] = bit * w_in[d] + b_in[d] + pos[p * D + d];
}

// ---------------- mask dtype detection ----------------
__global__ void mask_detect(const unsigned* __restrict__ km)
{
    __shared__ int sW, sF;
    if (threadIdx.x == 0) { sW = 0; sF = 0; }
    __syncthreads();
    int w = 0, f = 0;
    for (int i = threadIdx.x; i < N_TOK / 4; i += 256) {
        unsigned x = km[i];
        if (x == 0x3F800000u) f = 1;
        else if (x > 1u) w = 1;
    }
    if (w) atomicOr(&sW, 1);
    if (f) atomicOr(&sF, 1);
    __syncthreads();
    if (threadIdx.x == 0) g_maskmode = sW ? 2 : (sF ? 1 : 0);
}

// ---------------- build 27-bit window mask per token ----------------
__global__ void __launch_bounds__(256) mask_build(const void* __restrict__ km,
                                                  unsigned* __restrict__ mb)
{
    int n = blockIdx.x * blockDim.x + threadIdx.x;
    if (n >= N_TOK) return;
    int mode = g_maskmode;
    int b = n / V, c = n % V;
    int dc = c / 9, hc = (c % 9) / 3, wc = c % 3;
    unsigned bits = 0;
    #pragma unroll
    for (int l = 0; l < V; l++) {
        int nd = dc + l / 9 - 1;
        int nh = hc + (l % 9) / 3 - 1;
        int nw = wc + l % 3 - 1;
        if (nd < 0 || nd > 2 || nh < 0 || nh > 2 || nw < 0 || nw > 2) continue;
        int idx = b * V + nd * 9 + nh * 3 + nw;
        int val;
        if (mode == 2)      val = ((const unsigned char*)km)[idx] != 0;
        else if (mode == 1) val = ((const float*)km)[idx] != 0.0f;
        else                val = ((const int*)km)[idx] != 0;
        if (val) bits |= (1u << l);
    }
    mb[n] = bits;
}

// ---------------- layernorm: one warp per row, 8 elems/lane ------------------
__global__ void __launch_bounds__(256) ln_kernel(
    const float* __restrict__ x, const float* __restrict__ g,
    const float* __restrict__ b, float* __restrict__ y)
{
    int warp = threadIdx.x >> 5, lane = threadIdx.x & 31;
    int row = blockIdx.x * 8 + warp;
    const float* xr = &x[(size_t)row * D + lane * 8];
    float4 v0 = *reinterpret_cast<const float4*>(xr);
    float4 v1 = *reinterpret_cast<const float4*>(xr + 4);

    float sum = v0.x + v0.y + v0.z + v0.w + v1.x + v1.y + v1.z + v1.w;
    float sq  = v0.x*v0.x + v0.y*v0.y + v0.z*v0.z + v0.w*v0.w
              + v1.x*v1.x + v1.y*v1.y + v1.z*v1.z + v1.w*v1.w;
    #pragma unroll
    for (int o = 16; o; o >>= 1) {
        sum += __shfl_xor_sync(0xffffffffu, sum, o);
        sq  += __shfl_xor_sync(0xffffffffu, sq,  o);
    }
    float mu  = sum * (1.0f / D);
    float var = sq * (1.0f / D) - mu * mu;
    float rs  = rsqrtf(var + 1e-5f);

    float4 g0 = *reinterpret_cast<const float4*>(&g[lane * 8]);
    float4 g1 = *reinterpret_cast<const float4*>(&g[lane * 8 + 4]);
    float4 b0 = *reinterpret_cast<const float4*>(&b[lane * 8]);
    float4 b1 = *reinterpret_cast<const float4*>(&b[lane * 8 + 4]);

    float4 o0, o1;
    o0.x = (v0.x - mu) * rs * g0.x + b0.x;
    o0.y = (v0.y - mu) * rs * g0.y + b0.y;
    o0.z = (v0.z - mu) * rs * g0.z + b0.z;
    o0.w = (v0.w - mu) * rs * g0.w + b0.w;
    o1.x = (v1.x - mu) * rs * g1.x + b1.x;
    o1.y = (v1.y - mu) * rs * g1.y + b1.y;
    o1.z = (v1.z - mu) * rs * g1.z + b1.z;
    o1.w = (v1.w - mu) * rs * g1.w + b1.w;
    float* yr = &y[(size_t)row * D + lane * 8];
    *reinterpret_cast<float4*>(yr)     = o0;
    *reinterpret_cast<float4*>(yr + 4) = o1;
}

// ---------------- FP16 tensor-core GEMM body --------------------------------
// C[M,Nd] = A[M,K] @ W[K,Nd] + bias (+epilogue), via mma.m16n8k16 f16 (fp32 acc).
// 128x64x32 block tile, 8 warps (4m x 2n), warp tile 32x32 (2x4 frags).
// Smem rows stride 40 halves (80B): LDSM phases conflict-free, rows 16B-aligned.
// Fragments loaded with ldmatrix.m8n8.x4 (canonical mapping).
// EPI: 0 = bias, 1 = bias + residual, 2 = bias + exact gelu
template <int EPI>
__device__ __forceinline__ void gemm_body(
    __half (*As)[40], __half (*Bs)[40],
    const float* __restrict__ A, const float* __restrict__ W,
    const float* __restrict__ bias, float* __restrict__ C,
    int M, int K, int Nd)
{
    const int BK = 32;
    int m0 = blockIdx.y * 128, n0 = blockIdx.x * 64;
    int tid = threadIdx.x;
    int warp = tid >> 5, lane = tid & 31;
    int wm = (warp >> 1) * 32, wn = (warp & 1) * 32;
    int g = lane >> 2, tg = lane & 3;

    float acc[2][4][4] = {};

    // ldmatrix source coordinates (fixed per lane)
    int a_row = lane & 15;            // row within 16-row block
    int a_kh  = (lane >> 4) * 8;      // k-half offset (0 or 8)
    int b_q   = lane >> 3;            // quad 0..3
    int b_row = ((b_q >> 1) & 1) * 8 + (lane & 7);  // row within 16-row block
    int b_kh  = (b_q & 1) * 8;        // k-half offset

    // prefetch regs (global -> reg -> smem pipeline)
    float4 ra[4], rb[2];
    #pragma unroll
    for (int t = 0; t < 4; t++) {
        int i = tid + t * 256, row = i >> 3, c4 = i & 7;
        ra[t] = *reinterpret_cast<const float4*>(&A[(size_t)(m0 + row) * K + c4 * 4]);
    }
    #pragma unroll
    for (int t = 0; t < 2; t++) {
        int i = tid + t * 256, row = i >> 4, c4 = i & 15;
        rb[t] = *reinterpret_cast<const float4*>(&W[(size_t)row * Nd + n0 + c4 * 4]);
    }

    for (int k0 = 0; k0 < K; k0 += BK) {
        // A: store prefetched regs to smem as half2 pairs ([m][k])
        #pragma unroll
        for (int t = 0; t < 4; t++) {
            int i = tid + t * 256, row = i >> 3, c4 = i & 7;
            uint2 h;
            h.x = packh2(ra[t].x, ra[t].y);
            h.y = packh2(ra[t].z, ra[t].w);
            *reinterpret_cast<uint2*>(&As[row][c4 * 4]) = h;
        }
        // B: transpose W[k][n] -> Bs[n][k], half scatter
        #pragma unroll
        for (int t = 0; t < 2; t++) {
            int i = tid + t * 256, krow = i >> 4, c4 = i & 15;
            Bs[c4 * 4 + 0][krow] = __float2half_rn(rb[t].x);
            Bs[c4 * 4 + 1][krow] = __float2half_rn(rb[t].y);
            Bs[c4 * 4 + 2][krow] = __float2half_rn(rb[t].z);
            Bs[c4 * 4 + 3][krow] = __float2half_rn(rb[t].w);
        }
        __syncthreads();

        // next tile's global loads in flight during the mma work
        if (k0 + BK < K) {
            #pragma unroll
            for (int t = 0; t < 4; t++) {
                int i = tid + t * 256, row = i >> 3, c4 = i & 7;
                ra[t] = *reinterpret_cast<const float4*>(
                    &A[(size_t)(m0 + row) * K + k0 + BK + c4 * 4]);
            }
            #pragma unroll
            for (int t = 0; t < 2; t++) {
                int i = tid + t * 256, row = i >> 4, c4 = i & 15;
                rb[t] = *reinterpret_cast<const float4*>(
                    &W[(size_t)(k0 + BK + row) * Nd + n0 + c4 * 4]);
            }
        }

        #pragma unroll
        for (int ks = 0; ks < 2; ks++) {
            int kb = ks * 16;
            unsigned af[2][4], bf[4][2];
            // A fragments: one LDSM.x4 per 16-row block
            #pragma unroll
            for (int i = 0; i < 2; i++) {
                uint32_t addr = (uint32_t)__cvta_generic_to_shared(
                    &As[wm + i * 16 + a_row][kb + a_kh]);
                LDSM_X4(af[i][0], af[i][1], af[i][2], af[i][3], addr);
            }
            // B fragments: one LDSM.x4 per pair of j-blocks
            #pragma unroll
            for (int jj = 0; jj < 2; jj++) {
                uint32_t addr = (uint32_t)__cvta_generic_to_shared(
                    &Bs[wn + jj * 16 + b_row][kb + b_kh]);
                LDSM_X4(bf[jj * 2][0], bf[jj * 2][1],
                        bf[jj * 2 + 1][0], bf[jj * 2 + 1][1], addr);
            }
            #pragma unroll
            for (int i = 0; i < 2; i++)
                #pragma unroll
                for (int j = 0; j < 4; j++)
                    MMA_F16(acc[i][j][0], acc[i][j][1], acc[i][j][2], acc[i][j][3],
                            af[i][0], af[i][1], af[i][2], af[i][3],
                            bf[j][0], bf[j][1]);
        }
        __syncthreads();
    }

    // epilogue
    #pragma unroll
    for (int i = 0; i < 2; i++) {
        int r0 = m0 + wm + i * 16 + g;
        #pragma unroll
        for (int j = 0; j < 4; j++) {
            int c0 = n0 + wn + j * 8 + tg * 2;
            #pragma unroll
            for (int e = 0; e < 4; e++) {
                int gm = r0 + (e >> 1) * 8;
                int gn = c0 + (e & 1);
                float vv = acc[i][j][e] + bias[gn];
                if (EPI == 1) vv += C[(size_t)gm * Nd + gn];
                if (EPI == 2) vv = 0.5f * vv * (1.0f + erff(vv * 0.7071067811865475f));
                C[(size_t)gm * Nd + gn] = vv;
            }
        }
    }
}

// single-GEMM wrapper
template <int EPI>
__global__ void __launch_bounds__(256) gemm_tc(
    const float* __restrict__ A, const float* __restrict__ W,
    const float* __restrict__ bias, float* __restrict__ C,
    int M, int K, int Nd)
{
    __shared__ __align__(16) __half As[128][40];
    __shared__ __align__(16) __half Bs[64][40];
    gemm_body<EPI>(As, Bs, A, W, bias, C, M, K, Nd);
}

// fused Q/K/V wrapper: blockIdx.z selects which GEMM this CTA computes.
// Q reads tn (LN1 output); K/V read raw t. All ready after ln_kernel.
__global__ void __launch_bounds__(256) gemm_qkv(
    const float* __restrict__ tn, const float* __restrict__ t,
    const float* __restrict__ Wq, const float* __restrict__ bq,
    const float* __restrict__ Wk, const float* __restrict__ bk,
    const float* __restrict__ Wv, const float* __restrict__ bv,
    float* __restrict__ q, float* __restrict__ k, float* __restrict__ v,
    int M, int K, int Nd)
{
    __shared__ __align__(16) __half As[128][40];
    __shared__ __align__(16) __half Bs[64][40];
    if (blockIdx.z == 0)      gemm_body<0>(As, Bs, tn, Wq, bq, q, M, K, Nd);
    else if (blockIdx.z == 1) gemm_body<0>(As, Bs, t,  Wk, bk, k, M, K, Nd);
    else                      gemm_body<0>(As, Bs, t,  Wv, bv, v, M, K, Nd);
}

// ---------------- windowed attention: warp per head, block per token --------
__global__ void __launch_bounds__(256) attn_kernel(
    const float* __restrict__ q, const float* __restrict__ k,
    const float* __restrict__ v, const unsigned* __restrict__ mb,
    float* __restrict__ ao)
{
    int n = blockIdx.x;
    int h = threadIdx.x >> 5, lane = threadIdx.x & 31;
    int b = n / V, c = n % V;
    int dc = c / 9, hc = (c % 9) / 3, wc = c % 3;
    unsigned bits = mb[n];
    const float scale = 0.17677669529663687f;   // 1/sqrt(32)

    float qv = q[n * D + h * 32 + lane];
    float s_mine = -1e30f;

    #pragma unroll
    for (int l = 0; l < V; l++) {
        if (!((bits >> l) & 1)) continue;
        int nd = dc + l / 9 - 1, nh = hc + (l % 9) / 3 - 1, nw = wc + l % 3 - 1;
        int nn = b * V + nd * 9 + nh * 3 + nw;
        float p = qv * k[nn * D + h * 32 + lane];
        float s = warpSum(p) * scale;
        if (lane == l) s_mine = s;
    }

    float m = warpMax(s_mine);
    float e = (s_mine > -1e29f) ? __expf(s_mine - m) : 0.0f;
    float denom = warpSum(e);
    float a_mine = (denom > 0.0f) ? e / denom : 0.0f;

    float o = 0.0f;
    #pragma unroll
    for (int l = 0; l < V; l++) {
        float al = __shfl_sync(0xffffffffu, a_mine, l);
        if (!((bits >> l) & 1)) continue;
        if (al == 0.0f) continue;
        int nd = dc + l / 9 - 1, nh = hc + (l % 9) / 3 - 1, nw = wc + l % 3 - 1;
        int nn = b * V + nd * 9 + nh * 3 + nw;
        o += al * v[nn * D + h * 32 + lane];
    }
    ao[n * D + h * 32 + lane] = o;
}

// ---------------- final projection: out[b] = t[center] . w_out + b_out -----
__global__ void __launch_bounds__(256) out_kernel(
    const float* __restrict__ t, const float* __restrict__ wout,
    const float* __restrict__ bout, float* __restrict__ out)
{
    int b = blockIdx.x, tidx = threadIdx.x;
    float val = t[(b * V + 13) * D + tidx] * wout[tidx];
    __shared__ float s1[8];
    #pragma unroll
    for (int o = 16; o; o >>= 1) val += __shfl_xor_sync(0xffffffffu, val, o);
    if ((tidx & 31) == 0) s1[tidx >> 5] = val;
    __syncthreads();
    if (tidx == 0) {
        float s = 0.f;
        #pragma unroll
        for (int i = 0; i < 8; i++) s += s1[i];
        out[b] = s + bout[0];
    }
}

// ---------------- launch ----------------
extern "C" void kernel_launch(void* const* d_in, const int* in_sizes, int n_in,
                              void* d_out, int out_size)
{
    const float* npat = (const float*)d_in[0];
    const void*  km   = d_in[1];
    const float* w_in = (const float*)d_in[2];
    const float* b_in = (const float*)d_in[3];
    const float* pos  = (const float*)d_in[4];
    const float* ln1g = (const float*)d_in[5];
    const float* ln1b = (const float*)d_in[6];
    const float* ln2g = (const float*)d_in[7];
    const float* ln2b = (const float*)d_in[8];
    const float* Wq = (const float*)d_in[9];  const float* bq = (const float*)d_in[10];
    const float* Wk = (const float*)d_in[11]; const float* bk = (const float*)d_in[12];
    const float* Wv = (const float*)d_in[13]; const float* bv = (const float*)d_in[14];
    const float* Wo = (const float*)d_in[15]; const float* bo = (const float*)d_in[16];
    const float* W1 = (const float*)d_in[17]; const float* b1 = (const float*)d_in[18];
    const float* W2 = (const float*)d_in[19]; const float* b2 = (const float*)d_in[20];
    const float* wout = (const float*)d_in[21];
    const float* bout = (const float*)d_in[22];
    float* out = (float*)d_out;

    float *t, *tn, *q, *k, *v, *ao, *h;
    unsigned* mask;
    cudaGetSymbolAddress((void**)&t,  g_t);
    cudaGetSymbolAddress((void**)&tn, g_tn);
    cudaGetSymbolAddress((void**)&q,  g_q);
    cudaGetSymbolAddress((void**)&k,  g_k);
    cudaGetSymbolAddress((void**)&v,  g_v);
    cudaGetSymbolAddress((void**)&ao, g_ao);
    cudaGetSymbolAddress((void**)&h,  g_h);
    cudaGetSymbolAddress((void**)&mask, g_mask);

    embed_kernel<<<N_TOK, 256>>>(npat, w_in, b_in, pos, t);
    mask_detect<<<1, 256>>>((const unsigned*)km);
    mask_build<<<(N_TOK + 255) / 256, 256>>>(km, mask);

    dim3 gD(D / 64, N_TOK / 128);        // (4,54)
    dim3 gQKV(D / 64, N_TOK / 128, 3);   // (4,54,3)
    dim3 gF1(FF / 64, N_TOK / 128);      // (16,54)

    for (int l = 0; l < NLAYERS; l++) {
        const float* wq = Wq + (size_t)l * D * D;   const float* vbq = bq + l * D;
        const float* wk = Wk + (size_t)l * D * D;   const float* vbk = bk + l * D;
        const float* wv = Wv + (size_t)l * D * D;   const float* vbv = bv + l * D;
        const float* wo = Wo + (size_t)l * D * D;   const float* vbo = bo + l * D;
        const float* w1 = W1 + (size_t)l * D * FF;  const float* vb1 = b1 + l * FF;
        const float* w2 = W2 + (size_t)l * FF * D;  const float* vb2 = b2 + l * D;

        ln_kernel<<<N_TOK / 8, 256>>>(t, ln1g + l * D, ln1b + l * D, tn);
        gemm_qkv<<<gQKV, 256>>>(tn, t, wq, vbq, wk, vbk, wv, vbv,
                                q, k, v, N_TOK, D, D);
        attn_kernel<<<N_TOK, 256>>>(q, k, v, mask, ao);
        gemm_tc<1><<<gD, 256>>>(ao, wo, vbo, t, N_TOK, D, D);   // residual add
        ln_kernel<<<N_TOK / 8, 256>>>(t, ln2g + l * D, ln2b + l * D, tn);
        gemm_tc<2><<<gF1, 256>>>(tn, w1, vb1, h, N_TOK, D, FF); // gelu
        gemm_tc<1><<<gD, 256>>>(h, w2, vb2, t, N_TOK, FF, D);   // residual add
    }

    out_kernel<<<256, 256>>>(t, wout, bout, out);
}